// round 12
// baseline (speedup 1.0000x reference)
#include <cuda_runtime.h>
#include <cuda_fp16.h>
#include <cstdint>

// Problem constants
#define B_SZ   256
#define T_SZ   2049
#define D_SZ   64
#define NI_SZ  128
#define OUT_SZ 10
#define L_SZ   2080
#define S_SZ   16
#define BN_TOT 32768          // GEMM M
#define NBP    8320           // GEMM N: 8192 (W2) + 64 (b2) + 64 zero
#define KD2    2112           // GEMM K padded: 33 iters of 64
#define BM     128
#define BN     128
#define BK     64
#define NKIT   (KD2 / BK)     // 33
#define STAGE_B 65536         // A 32KB + B 32KB (256B rows: [fp16 128B|q8 64B|q2 64B])

// Scratch (device globals; allocation-free)
__device__ __half  g_ls_h [(size_t)BN_TOT * KD2];   // 138 MB fp16 main
__device__ __align__(16) int8_t g_ls_q8[(size_t)BN_TOT * KD2];  // 69 MB int8(v)
__device__ __align__(16) int8_t g_ls_q2[(size_t)BN_TOT * KD2];  // 69 MB int8(residual*2048)
__device__ __half  g_B_h  [(size_t)NBP * KD2];      // 35 MB
__device__ __align__(16) int8_t g_B_q8 [(size_t)NBP * KD2];
__device__ __align__(16) int8_t g_B_q2 [(size_t)NBP * KD2];
__device__ float g_ls_s[BN_TOT];
__device__ float g_B_s [NBP];
__device__ float g_V   [(size_t)BN_TOT * NBP];      // 1.09 GB

__device__ __forceinline__ void cp16s(uint32_t saddr, const void* g) {
    asm volatile("cp.async.cg.shared.global [%0], [%1], 16;" :: "r"(saddr), "l"(g));
}

// Block-wide (256 thr): reduce |max|, then write fp16 main + int8(v) + int8
// residual (scale locked to sa8/2048). rowv[KD2] in smem.
__device__ __forceinline__ void quant_row(const float* rowv, float* red, int t,
                                          __half* hh, int8_t* q8, int8_t* q2,
                                          float* s_out) {
    float mx = 0.0f;
    for (int i = t; i < KD2; i += 256) mx = fmaxf(mx, fabsf(rowv[i]));
    red[t] = mx;
    __syncthreads();
    #pragma unroll
    for (int off = 128; off > 0; off >>= 1) {
        if (t < off) red[t] = fmaxf(red[t], red[t + off]);
        __syncthreads();
    }
    mx = red[0];
    float inv = (mx > 0.0f) ? 127.0f / mx : 0.0f;
    for (int i = t; i < KD2; i += 256) {
        float v = rowv[i];
        __half h = __float2half_rn(v);
        hh[i] = h;
        int a1 = __float2int_rn(v * inv);
        a1 = max(-127, min(127, a1));
        int a2 = __float2int_rn((v - __half2float(h)) * inv * 2048.0f);
        a2 = max(-127, min(127, a2));
        q8[i] = (int8_t)a1;
        q2[i] = (int8_t)a2;
    }
    if (t == 0) *s_out = (mx > 0.0f) ? mx / 127.0f : 1.0f;
}

// ---------------------------------------------------------------------------
// Kernel 0: B rows = [W2 flat (8192); b2 (64); zeros].
// ---------------------------------------------------------------------------
__global__ void prep_B_k(const float* __restrict__ W2, const float* __restrict__ b2) {
    __shared__ float rowv[KD2];
    __shared__ float red[256];
    int r = blockIdx.x, t = threadIdx.x;
    const float* src = nullptr;
    if (r < 8192)       src = W2 + (size_t)r * L_SZ;
    else if (r < 8256)  src = b2 + (size_t)(r - 8192) * L_SZ;
    for (int i = t; i < KD2; i += 256)
        rowv[i] = (src && i < L_SZ) ? src[i] : 0.0f;
    __syncthreads();
    quant_row(rowv, red, t, g_B_h + (size_t)r * KD2, g_B_q8 + (size_t)r * KD2,
              g_B_q2 + (size_t)r * KD2, &g_B_s[r]);
}

// ---------------------------------------------------------------------------
// Kernel 1: depth-2 log-signature per (b, n) -> fp16 + int8 limbs.
// ---------------------------------------------------------------------------
__global__ void logsig_k(const float* __restrict__ X) {
    __shared__ float seg[17 * 64];
    __shared__ float cumS[16 * 64];
    __shared__ float dltS[16 * 64];
    __shared__ float Ms[64 * 64];
    __shared__ float rowv[KD2];
    __shared__ float red[256];

    int n = blockIdx.x, b = blockIdx.y;
    int bn = b * NI_SZ + n;
    int t = threadIdx.x;

    const float4* xp4 = (const float4*)(X + ((size_t)b * T_SZ + (size_t)n * S_SZ) * D_SZ);
    float4* seg4 = (float4*)seg;
    for (int i = t; i < 17 * 64 / 4; i += 256) seg4[i] = xp4[i];
    __syncthreads();

    for (int i = t; i < 16 * 64; i += 256) {
        int k = i >> 6, d = i & 63;
        cumS[i] = seg[k * 64 + d] - seg[d];
        dltS[i] = seg[(k + 1) * 64 + d] - seg[k * 64 + d];
    }
    __syncthreads();

    if (t < 64) rowv[t] = seg[16 * 64 + t] - seg[t];
    if (t < 32) rowv[2080 + t] = 0.0f;

    {
        int i = t >> 2;
        int jb = (t & 3) * 16;
        float acc[16];
        #pragma unroll
        for (int q = 0; q < 16; ++q) acc[q] = 0.0f;
        #pragma unroll
        for (int k = 0; k < 16; ++k) {
            float ci = cumS[k * 64 + i];
            const float4* dl4 = (const float4*)(dltS + k * 64 + jb);
            #pragma unroll
            for (int q4 = 0; q4 < 4; ++q4) {
                float4 dv = dl4[q4];
                acc[q4 * 4 + 0] += ci * dv.x;
                acc[q4 * 4 + 1] += ci * dv.y;
                acc[q4 * 4 + 2] += ci * dv.z;
                acc[q4 * 4 + 3] += ci * dv.w;
            }
        }
        float4* mrow = (float4*)(Ms + i * 64 + jb);
        #pragma unroll
        for (int q4 = 0; q4 < 4; ++q4)
            mrow[q4] = make_float4(acc[q4 * 4 + 0], acc[q4 * 4 + 1],
                                   acc[q4 * 4 + 2], acc[q4 * 4 + 3]);
    }
    __syncthreads();

    for (int p = t; p < 2016; p += 256) {
        int i = 0, rs = 0;
        while (rs + (63 - i) <= p) { rs += 63 - i; ++i; }
        int j = i + 1 + (p - rs);
        rowv[64 + p] = 0.5f * (Ms[i * 64 + j] - Ms[j * 64 + i]);
    }
    __syncthreads();

    quant_row(rowv, red, t, g_ls_h + (size_t)bn * KD2, g_ls_q8 + (size_t)bn * KD2,
              g_ls_q2 + (size_t)bn * KD2, &g_ls_s[bn]);
}

// ---------------------------------------------------------------------------
// Kernel 2: hybrid TN GEMM. Main Ah*Bh via m16n8k16.f16 fp32-acc;
// corrections (Al8*B8 + A8*Bl8) share one s32 acc via m16n8k32.s8
// (locked scales: sal = sa8/2048). V = main + sa8*sb8/2048 * c12.
// CTA 128x128x64, 8 warps (2x4), warp 64x32. Rows 256B = 16 chunks
// [fp16 c0-7 | q8 c8-11 | q2 c12-15], XOR swizzle on low 3 chunk bits.
// 2-stage cp.async, trailing barrier (proven schedule).
// ---------------------------------------------------------------------------
__device__ __forceinline__ void ldsm4(uint32_t* r, uint32_t addr) {
    asm volatile("ldmatrix.sync.aligned.m8n8.x4.shared.b16 {%0,%1,%2,%3}, [%4];"
                 : "=r"(r[0]), "=r"(r[1]), "=r"(r[2]), "=r"(r[3]) : "r"(addr));
}
__device__ __forceinline__ void mma_f16(float* c, const uint32_t* a, const uint32_t* b) {
    asm volatile(
        "mma.sync.aligned.m16n8k16.row.col.f32.f16.f16.f32 "
        "{%0,%1,%2,%3}, {%4,%5,%6,%7}, {%8,%9}, {%0,%1,%2,%3};"
        : "+f"(c[0]), "+f"(c[1]), "+f"(c[2]), "+f"(c[3])
        : "r"(a[0]), "r"(a[1]), "r"(a[2]), "r"(a[3]), "r"(b[0]), "r"(b[1]));
}
__device__ __forceinline__ void mma_s8(int* c, const uint32_t* a, const uint32_t* b) {
    asm volatile(
        "mma.sync.aligned.m16n8k32.row.col.s32.s8.s8.s32 "
        "{%0,%1,%2,%3}, {%4,%5,%6,%7}, {%8,%9}, {%0,%1,%2,%3};"
        : "+r"(c[0]), "+r"(c[1]), "+r"(c[2]), "+r"(c[3])
        : "r"(a[0]), "r"(a[1]), "r"(a[2]), "r"(a[3]), "r"(b[0]), "r"(b[1]));
}
#define SW(c, row) ((uint32_t)((((c) & 8) | (((c) ^ (row)) & 7)) << 4))

__global__ void __launch_bounds__(256) gemm_k() {
    extern __shared__ uint8_t dsm_raw[];
    uint32_t base0 = (uint32_t)__cvta_generic_to_shared(dsm_raw);
    uint32_t sbase = (base0 + 1023) & ~1023u;

    int tid  = threadIdx.x;
    int lane = tid & 31;
    int wid  = tid >> 5;
    int g    = lane >> 2;
    int tig  = lane & 3;
    int wm   = (wid & 1) * 64;
    int wn   = (wid >> 1) * 32;
    int ntile = blockIdx.x, mtile = blockIdx.y;

    const __half* Ahp = g_ls_h  + (size_t)(mtile * BM) * KD2;
    const int8_t* A8p = g_ls_q8 + (size_t)(mtile * BM) * KD2;
    const int8_t* A2p = g_ls_q2 + (size_t)(mtile * BM) * KD2;
    const __half* Bhp = g_B_h   + (size_t)(ntile * BN) * KD2;
    const int8_t* B8p = g_B_q8  + (size_t)(ntile * BN) * KD2;
    const int8_t* B2p = g_B_q2  + (size_t)(ntile * BN) * KD2;

    float c[4][4][4];
    int   c12[4][4][4];
    #pragma unroll
    for (int mi = 0; mi < 4; ++mi)
        #pragma unroll
        for (int ni = 0; ni < 4; ++ni)
            #pragma unroll
            for (int q = 0; q < 4; ++q) { c[mi][ni][q] = 0.0f; c12[mi][ni][q] = 0; }

    // Per-thread staging constants: ch fixed, rows walk r0 + 16*i.
    int ch = tid & 15;
    int r0 = tid >> 4;             // 0..15
    uint32_t swc = SW(ch, r0);     // row&7 == r0&7 for all i

    auto stage = [&](int it2, int s) {
        uint32_t base = sbase + (uint32_t)s * STAGE_B;
        int kb = it2 * BK;
        const char* pA; const char* pB; size_t rstr;
        if (ch < 8) {
            pA = (const char*)(Ahp + kb) + ch * 16;
            pB = (const char*)(Bhp + kb) + ch * 16;
            rstr = (size_t)KD2 * 2;
        } else if (ch < 12) {
            pA = (const char*)(A8p + kb) + (ch - 8) * 16;
            pB = (const char*)(B8p + kb) + (ch - 8) * 16;
            rstr = (size_t)KD2;
        } else {
            pA = (const char*)(A2p + kb) + (ch - 12) * 16;
            pB = (const char*)(B2p + kb) + (ch - 12) * 16;
            rstr = (size_t)KD2;
        }
        #pragma unroll
        for (int i = 0; i < 16; ++i) {
            int row = r0 + i * 16;       // 0..255 (A: <128, B: >=128)
            const char* src = (i < 8) ? pA + (size_t)row * rstr
                                      : pB + (size_t)(row - 128) * rstr;
            cp16s(base + (uint32_t)row * 256 + swc, src);
        }
        asm volatile("cp.async.commit_group;");
    };

    stage(0, 0);

    for (int it = 0; it < NKIT; ++it) {
        int s = it & 1;
        if (it + 1 < NKIT) {
            stage(it + 1, s ^ 1);
            asm volatile("cp.async.wait_group 1;");
        } else {
            asm volatile("cp.async.wait_group 0;");
        }
        __syncthreads();

        uint32_t Ab = sbase + (uint32_t)s * STAGE_B;
        uint32_t Bb = Ab + 32768;

        // ---- main fp16: 4 k16 steps ----
        #pragma unroll
        for (int ks = 0; ks < 4; ++ks) {
            uint32_t ah[4][4], bh[4][2];
            #pragma unroll
            for (int mi = 0; mi < 4; ++mi) {
                int row = wm + mi * 16 + (lane & 15);
                int cc  = ks * 2 + (lane >> 4);
                ldsm4(ah[mi], Ab + row * 256 + SW(cc, row));
            }
            #pragma unroll
            for (int p = 0; p < 2; ++p) {
                int row = wn + p * 16 + ((lane >> 4) & 1) * 8 + (lane & 7);
                int cc  = ks * 2 + ((lane >> 3) & 1);
                uint32_t r4[4];
                ldsm4(r4, Bb + row * 256 + SW(cc, row));
                bh[2*p][0] = r4[0]; bh[2*p][1] = r4[1];
                bh[2*p+1][0] = r4[2]; bh[2*p+1][1] = r4[3];
            }
            #pragma unroll
            for (int mi = 0; mi < 4; ++mi)
                #pragma unroll
                for (int ni = 0; ni < 4; ++ni)
                    mma_f16(c[mi][ni], ah[mi], bh[ni]);
        }

        // ---- corrections s8: 2 k32 steps ----
        #pragma unroll
        for (int k2 = 0; k2 < 2; ++k2) {
            uint32_t a8[4][4], al[4][4], b8[4][2], bl[4][2];
            #pragma unroll
            for (int mi = 0; mi < 4; ++mi) {
                int row = wm + mi * 16 + (lane & 15);
                int kc  = lane >> 4;
                ldsm4(a8[mi], Ab + row * 256 + SW(8  + k2 * 2 + kc, row));
                ldsm4(al[mi], Ab + row * 256 + SW(12 + k2 * 2 + kc, row));
            }
            #pragma unroll
            for (int p = 0; p < 2; ++p) {
                int row = wn + p * 16 + ((lane >> 4) & 1) * 8 + (lane & 7);
                int kc  = (lane >> 3) & 1;
                uint32_t r4[4];
                ldsm4(r4, Bb + row * 256 + SW(8 + k2 * 2 + kc, row));
                b8[2*p][0] = r4[0]; b8[2*p][1] = r4[1];
                b8[2*p+1][0] = r4[2]; b8[2*p+1][1] = r4[3];
                ldsm4(r4, Bb + row * 256 + SW(12 + k2 * 2 + kc, row));
                bl[2*p][0] = r4[0]; bl[2*p][1] = r4[1];
                bl[2*p+1][0] = r4[2]; bl[2*p+1][1] = r4[3];
            }
            #pragma unroll
            for (int mi = 0; mi < 4; ++mi)
                #pragma unroll
                for (int ni = 0; ni < 4; ++ni) {
                    mma_s8(c12[mi][ni], al[mi], b8[ni]);
                    mma_s8(c12[mi][ni], a8[mi], bl[ni]);
                }
        }
        __syncthreads();   // protects buffer s^1 from next-iter staging
    }

    // Epilogue: V = main + sa8*sb8/2048 * c12
    int rowbase = mtile * BM + wm;
    int colbase = ntile * BN + wn;
    float sa[4][2], sb[4][2];
    #pragma unroll
    for (int mi = 0; mi < 4; ++mi) {
        sa[mi][0] = g_ls_s[rowbase + mi * 16 + g];
        sa[mi][1] = g_ls_s[rowbase + mi * 16 + g + 8];
    }
    #pragma unroll
    for (int ni = 0; ni < 4; ++ni) {
        sb[ni][0] = g_B_s[colbase + ni * 8 + tig * 2];
        sb[ni][1] = g_B_s[colbase + ni * 8 + tig * 2 + 1];
    }
    const float kinv = 1.0f / 2048.0f;
    #pragma unroll
    for (int mi = 0; mi < 4; ++mi) {
        #pragma unroll
        for (int ni = 0; ni < 4; ++ni) {
            int r0r = rowbase + mi * 16 + g;
            int cc  = colbase + ni * 8 + tig * 2;
            float v0 = c[mi][ni][0] + sa[mi][0] * sb[ni][0] * kinv * (float)c12[mi][ni][0];
            float v1 = c[mi][ni][1] + sa[mi][0] * sb[ni][1] * kinv * (float)c12[mi][ni][1];
            float v2 = c[mi][ni][2] + sa[mi][1] * sb[ni][0] * kinv * (float)c12[mi][ni][2];
            float v3 = c[mi][ni][3] + sa[mi][1] * sb[ni][1] * kinv * (float)c12[mi][ni][3];
            *(float2*)&g_V[(size_t)r0r * NBP + cc]       = make_float2(v0, v1);
            *(float2*)&g_V[(size_t)(r0r + 8) * NBP + cc] = make_float2(v2, v3);
        }
    }
}

// ---------------------------------------------------------------------------
// Kernel 3: RK4 scan (unchanged from round 9, passing).
// ---------------------------------------------------------------------------
#define VSLC 8256

__device__ __forceinline__ void hbar(int half) {
    asm volatile("bar.sync %0, 128;" :: "r"(half + 1) : "memory");
}

__global__ void __launch_bounds__(256) scan_k(
    const float* __restrict__ X,    const float* __restrict__ W_in,
    const float* __restrict__ b_in, const float* __restrict__ W1,
    const float* __restrict__ b1,   const float* __restrict__ W_out,
    const float* __restrict__ b_out, float* __restrict__ out)
{
    extern __shared__ float ssm[];
    float* VsA = ssm;
    float* hA  = ssm + 4 * VSLC;
    float* htA = hA + 128;
    float* zA  = htA + 128;
    float* ksA = zA + 256;

    int half = threadIdx.x >> 7;
    int t    = threadIdx.x & 127;
    int b    = blockIdx.x * 2 + half;

    float* h    = hA  + half * 64;
    float* ht   = htA + half * 64;
    float* z    = zA  + half * 128;
    float* ksum = ksA + half * 64;

    float w1r[64];
    #pragma unroll
    for (int i = 0; i < 64; ++i) w1r[i] = W1[i * 128 + t];
    float b1t = b1[t];

    if (t < 64) {
        float acc = b_in[t];
        const float* x0 = X + (size_t)b * T_SZ * D_SZ;
        #pragma unroll
        for (int d = 0; d < 64; ++d) acc += x0[d] * W_in[d * 64 + t];
        h[t] = acc; ht[t] = acc; ksum[t] = 0.0f;
    }

    uint32_t vs_s[2];
    vs_s[0] = (uint32_t)__cvta_generic_to_shared(VsA + (half * 2 + 0) * VSLC);
    vs_s[1] = (uint32_t)__cvta_generic_to_shared(VsA + (half * 2 + 1) * VSLC);

    auto prefetch = [&](int n, int buf) {
        const float* vg = g_V + (size_t)(b * NI_SZ + n) * NBP;
        uint32_t dst = vs_s[buf];
        for (int c4 = t; c4 < VSLC / 4; c4 += 128)
            cp16s(dst + c4 * 16, vg + c4 * 4);
        asm volatile("cp.async.commit_group;");
    };

    prefetch(0, 0);

    const float wgt[4] = {1.0f, 2.0f, 2.0f, 1.0f};
    const float aco[4] = {0.5f, 0.5f, 1.0f, 0.0f};

    for (int n = 0; n < NI_SZ; ++n) {
        asm volatile("cp.async.wait_group 0;");
        hbar(half);
        if (n + 1 < NI_SZ) prefetch(n + 1, (n + 1) & 1);
        const float* Vs = VsA + (half * 2 + (n & 1)) * VSLC;

        #pragma unroll
        for (int s = 0; s < 4; ++s) {
            float a0 = b1t, a1 = 0.0f, a2 = 0.0f, a3 = 0.0f;
            #pragma unroll
            for (int i = 0; i < 64; i += 4) {
                a0 += ht[i]     * w1r[i];
                a1 += ht[i + 1] * w1r[i + 1];
                a2 += ht[i + 2] * w1r[i + 2];
                a3 += ht[i + 3] * w1r[i + 3];
            }
            z[t] = tanhf((a0 + a1) + (a2 + a3));
            hbar(half);
            if (t < 64) {
                float k0 = Vs[128 * 64 + t], k1 = 0.0f, k2 = 0.0f, k3 = 0.0f;
                #pragma unroll
                for (int m = 0; m < 128; m += 4) {
                    k0 += z[m]     * Vs[m * 64 + t];
                    k1 += z[m + 1] * Vs[(m + 1) * 64 + t];
                    k2 += z[m + 2] * Vs[(m + 2) * 64 + t];
                    k3 += z[m + 3] * Vs[(m + 3) * 64 + t];
                }
                float ka = (k0 + k1) + (k2 + k3);
                ksum[t] += wgt[s] * ka;
                if (s < 3) ht[t] = h[t] + aco[s] * ka;
            }
            hbar(half);
        }
        if (t < 64) {
            float hn = h[t] + ksum[t] * (1.0f / 6.0f);
            h[t] = hn; ht[t] = hn; ksum[t] = 0.0f;
        }
    }

    if (t < OUT_SZ) {
        float acc = b_out[t];
        #pragma unroll
        for (int d = 0; d < 64; ++d) acc += h[d] * W_out[d * OUT_SZ + t];
        out[b * OUT_SZ + t] = acc;
    }
}

// ---------------------------------------------------------------------------
extern "C" void kernel_launch(void* const* d_in, const int* in_sizes, int n_in,
                              void* d_out, int out_size) {
    const float* X     = (const float*)d_in[0];
    const float* W_in  = (const float*)d_in[1];
    const float* b_in  = (const float*)d_in[2];
    const float* W1    = (const float*)d_in[3];
    const float* b1    = (const float*)d_in[4];
    const float* W2    = (const float*)d_in[5];
    const float* b2    = (const float*)d_in[6];
    const float* W_out = (const float*)d_in[7];
    const float* b_out = (const float*)d_in[8];
    float* out = (float*)d_out;

    (void)in_sizes; (void)n_in; (void)out_size;

    int gemm_smem = 2 * STAGE_B + 1024;                       // 132096
    cudaFuncSetAttribute(gemm_k, cudaFuncAttributeMaxDynamicSharedMemorySize, gemm_smem);
    int scan_smem = (4 * VSLC + 128 + 128 + 256 + 128) * 4;   // 134656
    cudaFuncSetAttribute(scan_k, cudaFuncAttributeMaxDynamicSharedMemorySize, scan_smem);

    prep_B_k<<<NBP, 256>>>(W2, b2);
    logsig_k<<<dim3(NI_SZ, B_SZ), 256>>>(X);
    gemm_k<<<dim3(NBP / BN, BN_TOT / BM), 256, gemm_smem>>>();
    scan_k<<<B_SZ / 2, 256, scan_smem>>>(X, W_in, b_in, W1, b1, W_out, b_out, out);
}

// round 13
// speedup vs baseline: 2.1541x; 2.1541x over previous
#include <cuda_runtime.h>
#include <cuda_fp16.h>
#include <cstdint>

// Problem constants
#define B_SZ   256
#define T_SZ   2049
#define D_SZ   64
#define NI_SZ  128
#define OUT_SZ 10
#define L_SZ   2080
#define S_SZ   16
#define BN_TOT 32768          // GEMM M
#define NBP    8320           // GEMM N: 8192 (W2) + 64 (b2) + 64 zero
#define KD     2080           // GEMM K: 65 iters of 32
#define BM     128
#define BN     128
#define BK     32
#define NKIT   (KD / BK)      // 65
#define STAGE_B 32768         // A 16KB + B 16KB per stage
#define LSCL   2048.0f        // lo-limb prescale (2^11, exact)

// Scratch (device globals; allocation-free)
__device__ __half g_ls_hi[(size_t)BN_TOT * KD];   // 136 MB
__device__ __half g_ls_lo[(size_t)BN_TOT * KD];   // 136 MB (prescaled x2048)
__device__ __half g_B_hi [(size_t)NBP * KD];      // 34.6 MB
__device__ __half g_B_lo [(size_t)NBP * KD];      // 34.6 MB (prescaled x2048)
__device__ float  g_V    [(size_t)BN_TOT * NBP];  // 1.09 GB

__device__ __forceinline__ void hsplit(float v, __half& h, __half& l) {
    h = __float2half_rn(v);
    l = __float2half_rn(LSCL * (v - __half2float(h)));
}
__device__ __forceinline__ void cp16s(uint32_t saddr, const void* g) {
    asm volatile("cp.async.cg.shared.global [%0], [%1], 16;" :: "r"(saddr), "l"(g));
}

// ---------------------------------------------------------------------------
// Kernel 0: B rows = [W2 flat (8192); b2 (64); zeros (64)], fp16 hi/lo.
// ---------------------------------------------------------------------------
__global__ void prep_B_k(const float* __restrict__ W2, const float* __restrict__ b2) {
    int r = blockIdx.x;
    const float* src = nullptr;
    if (r < 8192)       src = W2 + (size_t)r * L_SZ;
    else if (r < 8256)  src = b2 + (size_t)(r - 8192) * L_SZ;
    size_t o = (size_t)r * KD;
    for (int l = threadIdx.x; l < KD; l += blockDim.x) {
        float v = src ? src[l] : 0.0f;
        __half h, lo;
        hsplit(v, h, lo);
        g_B_hi[o + l] = h;
        g_B_lo[o + l] = lo;
    }
}

// ---------------------------------------------------------------------------
// Kernel 1: depth-2 log-signature per (b, n), fp16 hi/lo output.
// ---------------------------------------------------------------------------
__global__ void logsig_k(const float* __restrict__ X) {
    __shared__ float seg[17 * 64];
    __shared__ float cumS[16 * 64];
    __shared__ float dltS[16 * 64];
    __shared__ float Ms[64 * 64];

    int n = blockIdx.x, b = blockIdx.y;
    size_t bno = (size_t)(b * NI_SZ + n) * KD;
    int t = threadIdx.x;

    const float4* xp4 = (const float4*)(X + ((size_t)b * T_SZ + (size_t)n * S_SZ) * D_SZ);
    float4* seg4 = (float4*)seg;
    for (int i = t; i < 17 * 64 / 4; i += 256) seg4[i] = xp4[i];
    __syncthreads();

    for (int i = t; i < 16 * 64; i += 256) {
        int k = i >> 6, d = i & 63;
        cumS[i] = seg[k * 64 + d] - seg[d];
        dltS[i] = seg[(k + 1) * 64 + d] - seg[k * 64 + d];
    }
    __syncthreads();

    if (t < 64) {
        __half h, lo;
        hsplit(seg[16 * 64 + t] - seg[t], h, lo);
        g_ls_hi[bno + t] = h; g_ls_lo[bno + t] = lo;
    }

    {
        int i = t >> 2;
        int jb = (t & 3) * 16;
        float acc[16];
        #pragma unroll
        for (int q = 0; q < 16; ++q) acc[q] = 0.0f;
        #pragma unroll
        for (int k = 0; k < 16; ++k) {
            float ci = cumS[k * 64 + i];
            const float4* dl4 = (const float4*)(dltS + k * 64 + jb);
            #pragma unroll
            for (int q4 = 0; q4 < 4; ++q4) {
                float4 dv = dl4[q4];
                acc[q4 * 4 + 0] += ci * dv.x;
                acc[q4 * 4 + 1] += ci * dv.y;
                acc[q4 * 4 + 2] += ci * dv.z;
                acc[q4 * 4 + 3] += ci * dv.w;
            }
        }
        float4* mrow = (float4*)(Ms + i * 64 + jb);
        #pragma unroll
        for (int q4 = 0; q4 < 4; ++q4)
            mrow[q4] = make_float4(acc[q4 * 4 + 0], acc[q4 * 4 + 1],
                                   acc[q4 * 4 + 2], acc[q4 * 4 + 3]);
    }
    __syncthreads();

    for (int p = t; p < 2016; p += 256) {
        int i = 0, rs = 0;
        while (rs + (63 - i) <= p) { rs += 63 - i; ++i; }
        int j = i + 1 + (p - rs);
        float a = 0.5f * (Ms[i * 64 + j] - Ms[j * 64 + i]);
        __half h, lo;
        hsplit(a, h, lo);
        g_ls_hi[bno + 64 + p] = h; g_ls_lo[bno + 64 + p] = lo;
    }
}

// ---------------------------------------------------------------------------
// Kernel 2: TN GEMM  g_V = ls @ B^T. Main ah*bh fp32-acc HMMA; both cross
// products (al*bh + ah*bl, lo prescaled x2048) share ONE fp16-acc HMMA
// accumulator. V = main + cross/2048. CTA 128x128x32, 8 warps (2x4),
// warp 64x32, 2-stage cp.async WITH trailing barrier (proven schedule).
// ---------------------------------------------------------------------------
__device__ __forceinline__ void ldsm4(uint32_t* r, uint32_t addr) {
    asm volatile("ldmatrix.sync.aligned.m8n8.x4.shared.b16 {%0,%1,%2,%3}, [%4];"
                 : "=r"(r[0]), "=r"(r[1]), "=r"(r[2]), "=r"(r[3]) : "r"(addr));
}
__device__ __forceinline__ void mma_f32acc(float* c, const uint32_t* a, const uint32_t* b) {
    asm volatile(
        "mma.sync.aligned.m16n8k16.row.col.f32.f16.f16.f32 "
        "{%0,%1,%2,%3}, {%4,%5,%6,%7}, {%8,%9}, {%0,%1,%2,%3};"
        : "+f"(c[0]), "+f"(c[1]), "+f"(c[2]), "+f"(c[3])
        : "r"(a[0]), "r"(a[1]), "r"(a[2]), "r"(a[3]), "r"(b[0]), "r"(b[1]));
}
__device__ __forceinline__ void mma_f16acc(uint32_t* c, const uint32_t* a, const uint32_t* b) {
    asm volatile(
        "mma.sync.aligned.m16n8k16.row.col.f16.f16.f16.f16 "
        "{%0,%1}, {%2,%3,%4,%5}, {%6,%7}, {%0,%1};"
        : "+r"(c[0]), "+r"(c[1])
        : "r"(a[0]), "r"(a[1]), "r"(a[2]), "r"(a[3]), "r"(b[0]), "r"(b[1]));
}

__global__ void __launch_bounds__(256) gemm_k() {
    extern __shared__ uint8_t dsm_raw[];
    uint32_t base0 = (uint32_t)__cvta_generic_to_shared(dsm_raw);
    uint32_t sbase = (base0 + 1023) & ~1023u;

    int tid  = threadIdx.x;
    int lane = tid & 31;
    int wid  = tid >> 5;
    int g    = lane >> 2;
    int tig  = lane & 3;
    int wm   = (wid & 1) * 64;
    int wn   = (wid >> 1) * 32;
    int ntile = blockIdx.x, mtile = blockIdx.y;

    const __half* Agh = g_ls_hi + (size_t)(mtile * BM) * KD;
    const __half* Agl = g_ls_lo + (size_t)(mtile * BM) * KD;
    const __half* Bgh = g_B_hi  + (size_t)(ntile * BN) * KD;
    const __half* Bgl = g_B_lo  + (size_t)(ntile * BN) * KD;

    float    c [4][4][4];   // main, fp32 acc
    uint32_t cx[4][4][2];   // cross, fp16x2 acc (prescaled x2048)
    #pragma unroll
    for (int mi = 0; mi < 4; ++mi)
        #pragma unroll
        for (int ni = 0; ni < 4; ++ni) {
            #pragma unroll
            for (int q = 0; q < 4; ++q) c[mi][ni][q] = 0.0f;
            cx[mi][ni][0] = 0u; cx[mi][ni][1] = 0u;
        }

    // Stage: A 128 rows + B 128 rows, each row 128B = [hi 64B | lo 64B]
    auto stage = [&](int it2, int s) {
        uint32_t base = sbase + (uint32_t)s * STAGE_B;
        int kb = it2 * BK;
        #pragma unroll
        for (int i = 0; i < 8; ++i) {
            int isB   = (i >= 4);
            int local = tid + i * 256 - isB * 1024;
            int row   = local >> 3;
            int ch    = local & 7;
            int hil   = ch >> 2;
            int ck    = ch & 3;
            const __half* src =
                (isB ? (hil ? Bgl : Bgh) + (size_t)row * KD
                     : (hil ? Agl : Agh) + (size_t)row * KD) + kb + ck * 8;
            uint32_t dst = base + (isB ? 16384u : 0u)
                         + (uint32_t)row * 128 + (uint32_t)((ch ^ (row & 7)) << 4);
            cp16s(dst, src);
        }
        asm volatile("cp.async.commit_group;");
    };

    stage(0, 0);

    for (int it = 0; it < NKIT; ++it) {
        int s = it & 1;
        if (it + 1 < NKIT) {
            stage(it + 1, s ^ 1);
            asm volatile("cp.async.wait_group 1;");
        } else {
            asm volatile("cp.async.wait_group 0;");
        }
        __syncthreads();

        uint32_t Ab = sbase + (uint32_t)s * STAGE_B;
        uint32_t Bb = Ab + 16384;

        #pragma unroll
        for (int ks = 0; ks < 2; ++ks) {
            uint32_t ah[4][4], al[4][4], bh[4][2], bl[4][2];
            #pragma unroll
            for (int mi = 0; mi < 4; ++mi) {
                int row = wm + mi * 16 + (lane & 15);
                int kc  = lane >> 4;
                ldsm4(ah[mi], Ab + row * 128 + (((ks * 2 + kc)     ^ (row & 7)) << 4));
                ldsm4(al[mi], Ab + row * 128 + (((4 + ks * 2 + kc) ^ (row & 7)) << 4));
            }
            #pragma unroll
            for (int p = 0; p < 2; ++p) {
                int row = wn + p * 16 + ((lane >> 4) & 1) * 8 + (lane & 7);
                int kc  = (lane >> 3) & 1;
                uint32_t r4[4];
                ldsm4(r4, Bb + row * 128 + (((ks * 2 + kc) ^ (row & 7)) << 4));
                bh[2*p][0] = r4[0]; bh[2*p][1] = r4[1];
                bh[2*p+1][0] = r4[2]; bh[2*p+1][1] = r4[3];
                ldsm4(r4, Bb + row * 128 + (((4 + ks * 2 + kc) ^ (row & 7)) << 4));
                bl[2*p][0] = r4[0]; bl[2*p][1] = r4[1];
                bl[2*p+1][0] = r4[2]; bl[2*p+1][1] = r4[3];
            }
            #pragma unroll
            for (int mi = 0; mi < 4; ++mi)
                #pragma unroll
                for (int ni = 0; ni < 4; ++ni) {
                    mma_f16acc(cx[mi][ni], al[mi], bh[ni]);
                    mma_f16acc(cx[mi][ni], ah[mi], bl[ni]);
                    mma_f32acc(c[mi][ni],  ah[mi], bh[ni]);
                }
        }
        __syncthreads();   // REQUIRED: protects buffer s^1 from next-iter staging
    }

    // Epilogue: V = main + cross / 2048
    const float kinv = 1.0f / LSCL;
    int rowbase = mtile * BM + wm;
    int colbase = ntile * BN + wn;
    #pragma unroll
    for (int mi = 0; mi < 4; ++mi) {
        #pragma unroll
        for (int ni = 0; ni < 4; ++ni) {
            int r0 = rowbase + mi * 16 + g;
            int cc = colbase + ni * 8 + tig * 2;
            float2 x0 = __half22float2(*(__half2*)&cx[mi][ni][0]);
            float2 x1 = __half22float2(*(__half2*)&cx[mi][ni][1]);
            *(float2*)&g_V[(size_t)r0 * NBP + cc] =
                make_float2(c[mi][ni][0] + kinv * x0.x, c[mi][ni][1] + kinv * x0.y);
            *(float2*)&g_V[(size_t)(r0 + 8) * NBP + cc] =
                make_float2(c[mi][ni][2] + kinv * x1.x, c[mi][ni][3] + kinv * x1.y);
        }
    }
}

// ---------------------------------------------------------------------------
// Kernel 3: RK4 scan (round-9 version, passing at 565us).
// ---------------------------------------------------------------------------
#define VSLC 8256

__device__ __forceinline__ void hbar(int half) {
    asm volatile("bar.sync %0, 128;" :: "r"(half + 1) : "memory");
}

__global__ void __launch_bounds__(256) scan_k(
    const float* __restrict__ X,    const float* __restrict__ W_in,
    const float* __restrict__ b_in, const float* __restrict__ W1,
    const float* __restrict__ b1,   const float* __restrict__ W_out,
    const float* __restrict__ b_out, float* __restrict__ out)
{
    extern __shared__ float ssm[];
    float* VsA = ssm;
    float* hA  = ssm + 4 * VSLC;
    float* htA = hA + 128;
    float* zA  = htA + 128;
    float* ksA = zA + 256;

    int half = threadIdx.x >> 7;
    int t    = threadIdx.x & 127;
    int b    = blockIdx.x * 2 + half;

    float* h    = hA  + half * 64;
    float* ht   = htA + half * 64;
    float* z    = zA  + half * 128;
    float* ksum = ksA + half * 64;

    float w1r[64];
    #pragma unroll
    for (int i = 0; i < 64; ++i) w1r[i] = W1[i * 128 + t];
    float b1t = b1[t];

    if (t < 64) {
        float acc = b_in[t];
        const float* x0 = X + (size_t)b * T_SZ * D_SZ;
        #pragma unroll
        for (int d = 0; d < 64; ++d) acc += x0[d] * W_in[d * 64 + t];
        h[t] = acc; ht[t] = acc; ksum[t] = 0.0f;
    }

    uint32_t vs_s[2];
    vs_s[0] = (uint32_t)__cvta_generic_to_shared(VsA + (half * 2 + 0) * VSLC);
    vs_s[1] = (uint32_t)__cvta_generic_to_shared(VsA + (half * 2 + 1) * VSLC);

    auto prefetch = [&](int n, int buf) {
        const float* vg = g_V + (size_t)(b * NI_SZ + n) * NBP;
        uint32_t dst = vs_s[buf];
        for (int c4 = t; c4 < VSLC / 4; c4 += 128)
            cp16s(dst + c4 * 16, vg + c4 * 4);
        asm volatile("cp.async.commit_group;");
    };

    prefetch(0, 0);

    const float wgt[4] = {1.0f, 2.0f, 2.0f, 1.0f};
    const float aco[4] = {0.5f, 0.5f, 1.0f, 0.0f};

    for (int n = 0; n < NI_SZ; ++n) {
        asm volatile("cp.async.wait_group 0;");
        hbar(half);
        if (n + 1 < NI_SZ) prefetch(n + 1, (n + 1) & 1);
        const float* Vs = VsA + (half * 2 + (n & 1)) * VSLC;

        #pragma unroll
        for (int s = 0; s < 4; ++s) {
            float a0 = b1t, a1 = 0.0f, a2 = 0.0f, a3 = 0.0f;
            #pragma unroll
            for (int i = 0; i < 64; i += 4) {
                a0 += ht[i]     * w1r[i];
                a1 += ht[i + 1] * w1r[i + 1];
                a2 += ht[i + 2] * w1r[i + 2];
                a3 += ht[i + 3] * w1r[i + 3];
            }
            z[t] = tanhf((a0 + a1) + (a2 + a3));
            hbar(half);
            if (t < 64) {
                float k0 = Vs[128 * 64 + t], k1 = 0.0f, k2 = 0.0f, k3 = 0.0f;
                #pragma unroll
                for (int m = 0; m < 128; m += 4) {
                    k0 += z[m]     * Vs[m * 64 + t];
                    k1 += z[m + 1] * Vs[(m + 1) * 64 + t];
                    k2 += z[m + 2] * Vs[(m + 2) * 64 + t];
                    k3 += z[m + 3] * Vs[(m + 3) * 64 + t];
                }
                float ka = (k0 + k1) + (k2 + k3);
                ksum[t] += wgt[s] * ka;
                if (s < 3) ht[t] = h[t] + aco[s] * ka;
            }
            hbar(half);
        }
        if (t < 64) {
            float hn = h[t] + ksum[t] * (1.0f / 6.0f);
            h[t] = hn; ht[t] = hn; ksum[t] = 0.0f;
        }
    }

    if (t < OUT_SZ) {
        float acc = b_out[t];
        #pragma unroll
        for (int d = 0; d < 64; ++d) acc += h[d] * W_out[d * OUT_SZ + t];
        out[b * OUT_SZ + t] = acc;
    }
}

// ---------------------------------------------------------------------------
extern "C" void kernel_launch(void* const* d_in, const int* in_sizes, int n_in,
                              void* d_out, int out_size) {
    const float* X     = (const float*)d_in[0];
    const float* W_in  = (const float*)d_in[1];
    const float* b_in  = (const float*)d_in[2];
    const float* W1    = (const float*)d_in[3];
    const float* b1    = (const float*)d_in[4];
    const float* W2    = (const float*)d_in[5];
    const float* b2    = (const float*)d_in[6];
    const float* W_out = (const float*)d_in[7];
    const float* b_out = (const float*)d_in[8];
    float* out = (float*)d_out;

    (void)in_sizes; (void)n_in; (void)out_size;

    int gemm_smem = 2 * STAGE_B + 1024;                       // 66560
    cudaFuncSetAttribute(gemm_k, cudaFuncAttributeMaxDynamicSharedMemorySize, gemm_smem);
    int scan_smem = (4 * VSLC + 128 + 128 + 256 + 128) * 4;   // 134656
    cudaFuncSetAttribute(scan_k, cudaFuncAttributeMaxDynamicSharedMemorySize, scan_smem);

    prep_B_k<<<NBP, 128>>>(W2, b2);
    logsig_k<<<dim3(NI_SZ, B_SZ), 256>>>(X);
    gemm_k<<<dim3(NBP / BN, BN_TOT / BM), 256, gemm_smem>>>();
    scan_k<<<B_SZ / 2, 256, scan_smem>>>(X, W_in, b_in, W1, b1, W_out, b_out, out);
}

// round 14
// speedup vs baseline: 2.4242x; 1.1254x over previous
#include <cuda_runtime.h>
#include <cuda_fp16.h>
#include <cstdint>

// Problem constants
#define B_SZ   256
#define T_SZ   2049
#define D_SZ   64
#define NI_SZ  128
#define OUT_SZ 10
#define L_SZ   2080
#define S_SZ   16
#define BN_TOT 32768          // GEMM M
#define NBP    8320           // GEMM N: 8192 (W2) + 64 (b2) + 64 zero
#define KD2    2112           // GEMM K padded: 33 iters of 64
#define BM     128
#define BN     128
#define BK     64
#define NKIT   (KD2 / BK)     // 33
#define STAGE_B 65536         // (BM+BN)=256 rows x 256B ([hi 128B | lo 128B])

// Scratch (device globals; allocation-free)
__device__ __half g_ls_hi[(size_t)BN_TOT * KD2];   // 138 MB
__device__ __half g_ls_lo[(size_t)BN_TOT * KD2];   // 138 MB
__device__ __half g_B_hi [(size_t)NBP * KD2];      // 35 MB
__device__ __half g_B_lo [(size_t)NBP * KD2];      // 35 MB
__device__ float  g_V    [(size_t)BN_TOT * NBP];   // 1.09 GB

__device__ __forceinline__ void hsplit(float v, __half& h, __half& l) {
    h = __float2half_rn(v);
    l = __float2half_rn(v - __half2float(h));
}
__device__ __forceinline__ void cp16s(uint32_t saddr, const void* g) {
    asm volatile("cp.async.cg.shared.global [%0], [%1], 16;" :: "r"(saddr), "l"(g));
}

// ---------------------------------------------------------------------------
// Kernel 0: B rows = [W2 flat (8192); b2 (64); zeros], fp16 hi/lo, K-padded.
// ---------------------------------------------------------------------------
__global__ void prep_B_k(const float* __restrict__ W2, const float* __restrict__ b2) {
    int r = blockIdx.x;
    const float* src = nullptr;
    if (r < 8192)       src = W2 + (size_t)r * L_SZ;
    else if (r < 8256)  src = b2 + (size_t)(r - 8192) * L_SZ;
    size_t o = (size_t)r * KD2;
    for (int l = threadIdx.x; l < KD2; l += blockDim.x) {
        float v = (src && l < L_SZ) ? src[l] : 0.0f;
        __half h, lo;
        hsplit(v, h, lo);
        g_B_hi[o + l] = h;
        g_B_lo[o + l] = lo;
    }
}

// ---------------------------------------------------------------------------
// Kernel 1: depth-2 log-signature per (b, n), fp16 hi/lo output, K-padded.
// ---------------------------------------------------------------------------
__global__ void logsig_k(const float* __restrict__ X) {
    __shared__ float seg[17 * 64];
    __shared__ float cumS[16 * 64];
    __shared__ float dltS[16 * 64];
    __shared__ float Ms[64 * 64];

    int n = blockIdx.x, b = blockIdx.y;
    size_t bno = (size_t)(b * NI_SZ + n) * KD2;
    int t = threadIdx.x;

    const float4* xp4 = (const float4*)(X + ((size_t)b * T_SZ + (size_t)n * S_SZ) * D_SZ);
    float4* seg4 = (float4*)seg;
    for (int i = t; i < 17 * 64 / 4; i += 256) seg4[i] = xp4[i];
    __syncthreads();

    for (int i = t; i < 16 * 64; i += 256) {
        int k = i >> 6, d = i & 63;
        cumS[i] = seg[k * 64 + d] - seg[d];
        dltS[i] = seg[(k + 1) * 64 + d] - seg[k * 64 + d];
    }
    __syncthreads();

    if (t < 64) {
        __half h, lo;
        hsplit(seg[16 * 64 + t] - seg[t], h, lo);
        g_ls_hi[bno + t] = h; g_ls_lo[bno + t] = lo;
    }
    if (t < 32) {   // zero K pad 2080..2111
        g_ls_hi[bno + 2080 + t] = __float2half_rn(0.0f);
        g_ls_lo[bno + 2080 + t] = __float2half_rn(0.0f);
    }

    {
        int i = t >> 2;
        int jb = (t & 3) * 16;
        float acc[16];
        #pragma unroll
        for (int q = 0; q < 16; ++q) acc[q] = 0.0f;
        #pragma unroll
        for (int k = 0; k < 16; ++k) {
            float ci = cumS[k * 64 + i];
            const float4* dl4 = (const float4*)(dltS + k * 64 + jb);
            #pragma unroll
            for (int q4 = 0; q4 < 4; ++q4) {
                float4 dv = dl4[q4];
                acc[q4 * 4 + 0] += ci * dv.x;
                acc[q4 * 4 + 1] += ci * dv.y;
                acc[q4 * 4 + 2] += ci * dv.z;
                acc[q4 * 4 + 3] += ci * dv.w;
            }
        }
        float4* mrow = (float4*)(Ms + i * 64 + jb);
        #pragma unroll
        for (int q4 = 0; q4 < 4; ++q4)
            mrow[q4] = make_float4(acc[q4 * 4 + 0], acc[q4 * 4 + 1],
                                   acc[q4 * 4 + 2], acc[q4 * 4 + 3]);
    }
    __syncthreads();

    for (int p = t; p < 2016; p += 256) {
        int i = 0, rs = 0;
        while (rs + (63 - i) <= p) { rs += 63 - i; ++i; }
        int j = i + 1 + (p - rs);
        float a = 0.5f * (Ms[i * 64 + j] - Ms[j * 64 + i]);
        __half h, lo;
        hsplit(a, h, lo);
        g_ls_hi[bno + 64 + p] = h; g_ls_lo[bno + 64 + p] = lo;
    }
}

// ---------------------------------------------------------------------------
// Kernel 2: TN GEMM  g_V = ls @ B^T, m16n8k16.f16 fp32-acc, 3-product split
// (al*bh + ah*bl + ah*bh). CTA 128x128x64, 8 warps (2x4), warp 64x32.
// Rows 256B = 16 chunks [hi c0-7 | lo c8-15], XOR swizzle (round-12 proven
// layout). 2-stage cp.async with trailing barrier (proven schedule).
// ---------------------------------------------------------------------------
__device__ __forceinline__ void ldsm4(uint32_t* r, uint32_t addr) {
    asm volatile("ldmatrix.sync.aligned.m8n8.x4.shared.b16 {%0,%1,%2,%3}, [%4];"
                 : "=r"(r[0]), "=r"(r[1]), "=r"(r[2]), "=r"(r[3]) : "r"(addr));
}
__device__ __forceinline__ void mma_f16(float* c, const uint32_t* a, const uint32_t* b) {
    asm volatile(
        "mma.sync.aligned.m16n8k16.row.col.f32.f16.f16.f32 "
        "{%0,%1,%2,%3}, {%4,%5,%6,%7}, {%8,%9}, {%0,%1,%2,%3};"
        : "+f"(c[0]), "+f"(c[1]), "+f"(c[2]), "+f"(c[3])
        : "r"(a[0]), "r"(a[1]), "r"(a[2]), "r"(a[3]), "r"(b[0]), "r"(b[1]));
}
#define SW(c, row) ((uint32_t)((((c) & 8) | (((c) ^ (row)) & 7)) << 4))

__global__ void __launch_bounds__(256) gemm_k() {
    extern __shared__ uint8_t dsm_raw[];
    uint32_t base0 = (uint32_t)__cvta_generic_to_shared(dsm_raw);
    uint32_t sbase = (base0 + 1023) & ~1023u;

    int tid  = threadIdx.x;
    int lane = tid & 31;
    int wid  = tid >> 5;
    int g    = lane >> 2;
    int tig  = lane & 3;
    int wm   = (wid & 1) * 64;
    int wn   = (wid >> 1) * 32;
    int ntile = blockIdx.x, mtile = blockIdx.y;

    const __half* Agh = g_ls_hi + (size_t)(mtile * BM) * KD2;
    const __half* Agl = g_ls_lo + (size_t)(mtile * BM) * KD2;
    const __half* Bgh = g_B_hi  + (size_t)(ntile * BN) * KD2;
    const __half* Bgl = g_B_lo  + (size_t)(ntile * BN) * KD2;

    float c[4][4][4];
    #pragma unroll
    for (int mi = 0; mi < 4; ++mi)
        #pragma unroll
        for (int ni = 0; ni < 4; ++ni)
            #pragma unroll
            for (int q = 0; q < 4; ++q) c[mi][ni][q] = 0.0f;

    // Staging (round-12 proven walk): ch fixed per thread, rows r0 + 16*i.
    int ch = tid & 15;
    int r0 = tid >> 4;
    uint32_t swc = SW(ch, r0);
    int cc8 = ch & 7;

    auto stage = [&](int it2, int s) {
        uint32_t base = sbase + (uint32_t)s * STAGE_B;
        int kb = it2 * BK;
        const char* pA; const char* pB;
        if (ch < 8) {
            pA = (const char*)(Agh + kb) + cc8 * 16;
            pB = (const char*)(Bgh + kb) + cc8 * 16;
        } else {
            pA = (const char*)(Agl + kb) + cc8 * 16;
            pB = (const char*)(Bgl + kb) + cc8 * 16;
        }
        #pragma unroll
        for (int i = 0; i < 16; ++i) {
            int row = r0 + i * 16;     // 0..255: A rows <128, B rows >=128
            const char* src = (i < 8) ? pA + (size_t)row * (KD2 * 2)
                                      : pB + (size_t)(row - 128) * (KD2 * 2);
            cp16s(base + (uint32_t)row * 256 + swc, src);
        }
        asm volatile("cp.async.commit_group;");
    };

    stage(0, 0);

    for (int it = 0; it < NKIT; ++it) {
        int s = it & 1;
        if (it + 1 < NKIT) {
            stage(it + 1, s ^ 1);
            asm volatile("cp.async.wait_group 1;");
        } else {
            asm volatile("cp.async.wait_group 0;");
        }
        __syncthreads();

        uint32_t Ab = sbase + (uint32_t)s * STAGE_B;
        uint32_t Bb = Ab + 128 * 256;

        #pragma unroll
        for (int ks = 0; ks < 4; ++ks) {
            uint32_t ah[4][4], al[4][4], bh[4][2], bl[4][2];
            #pragma unroll
            for (int mi = 0; mi < 4; ++mi) {
                int row = wm + mi * 16 + (lane & 15);
                int cc  = ks * 2 + (lane >> 4);
                ldsm4(ah[mi], Ab + row * 256 + SW(cc, row));
                ldsm4(al[mi], Ab + row * 256 + SW(8 + cc, row));
            }
            #pragma unroll
            for (int p = 0; p < 2; ++p) {
                int row = wn + p * 16 + ((lane >> 4) & 1) * 8 + (lane & 7);
                int cc  = ks * 2 + ((lane >> 3) & 1);
                uint32_t r4[4];
                ldsm4(r4, Bb + row * 256 + SW(cc, row));
                bh[2*p][0] = r4[0]; bh[2*p][1] = r4[1];
                bh[2*p+1][0] = r4[2]; bh[2*p+1][1] = r4[3];
                ldsm4(r4, Bb + row * 256 + SW(8 + cc, row));
                bl[2*p][0] = r4[0]; bl[2*p][1] = r4[1];
                bl[2*p+1][0] = r4[2]; bl[2*p+1][1] = r4[3];
            }
            #pragma unroll
            for (int mi = 0; mi < 4; ++mi)
                #pragma unroll
                for (int ni = 0; ni < 4; ++ni) {
                    mma_f16(c[mi][ni], al[mi], bh[ni]);
                    mma_f16(c[mi][ni], ah[mi], bl[ni]);
                    mma_f16(c[mi][ni], ah[mi], bh[ni]);
                }
        }
        __syncthreads();   // REQUIRED: protects buffer s^1 from next-iter staging
    }

    // Epilogue
    int rowbase = mtile * BM + wm;
    int colbase = ntile * BN + wn;
    #pragma unroll
    for (int mi = 0; mi < 4; ++mi) {
        #pragma unroll
        for (int ni = 0; ni < 4; ++ni) {
            int r0r = rowbase + mi * 16 + g;
            int cc = colbase + ni * 8 + tig * 2;
            *(float2*)&g_V[(size_t)r0r * NBP + cc] =
                make_float2(c[mi][ni][0], c[mi][ni][1]);
            *(float2*)&g_V[(size_t)(r0r + 8) * NBP + cc] =
                make_float2(c[mi][ni][2], c[mi][ni][3]);
        }
    }
}

// ---------------------------------------------------------------------------
// Kernel 3: RK4 scan. 128 CTAs x 256 threads; 2 batch elems per CTA.
// V prefetch via ONE cp.async.bulk (33KB, mbarrier complete_tx) per half
// per interval — removes the 4128 per-16B cp.async issue bottleneck.
// ---------------------------------------------------------------------------
#define VSLC 8256                    // 129*64 floats per interval slice
#define VBYTES (VSLC * 4)            // 33024 B per bulk copy

__device__ __forceinline__ void hbar(int half) {
    asm volatile("bar.sync %0, 128;" :: "r"(half + 1) : "memory");
}
__device__ __forceinline__ void mbar_init(uint32_t addr, uint32_t cnt) {
    asm volatile("mbarrier.init.shared.b64 [%0], %1;" :: "r"(addr), "r"(cnt) : "memory");
}
__device__ __forceinline__ void mbar_expect_tx(uint32_t addr, uint32_t bytes) {
    asm volatile("mbarrier.arrive.expect_tx.shared.b64 _, [%0], %1;"
                 :: "r"(addr), "r"(bytes) : "memory");
}
__device__ __forceinline__ void bulk_g2s(uint32_t dst, const void* src,
                                         uint32_t bytes, uint32_t mbar) {
    asm volatile(
        "cp.async.bulk.shared::cluster.global.mbarrier::complete_tx::bytes "
        "[%0], [%1], %2, [%3];"
        :: "r"(dst), "l"(src), "r"(bytes), "r"(mbar) : "memory");
}
__device__ __forceinline__ void mbar_wait(uint32_t addr, uint32_t parity) {
    asm volatile("{\n\t.reg .pred P;\n\tWL_%=:\n\t"
                 "mbarrier.try_wait.parity.acquire.cta.shared::cta.b64 P, [%0], %1, 0x989680;\n\t"
                 "@P bra.uni WD_%=;\n\tbra.uni WL_%=;\n\tWD_%=:\n\t}"
                 :: "r"(addr), "r"(parity) : "memory");
}

__global__ void __launch_bounds__(256) scan_k(
    const float* __restrict__ X,    const float* __restrict__ W_in,
    const float* __restrict__ b_in, const float* __restrict__ W1,
    const float* __restrict__ b1,   const float* __restrict__ W_out,
    const float* __restrict__ b_out, float* __restrict__ out)
{
    extern __shared__ float ssm[];
    __shared__ __align__(8) uint64_t mbar_s[4];   // [half*2 + buf]

    float* VsA = ssm;
    float* hA  = ssm + 4 * VSLC;
    float* htA = hA + 128;
    float* zA  = htA + 128;
    float* ksA = zA + 256;

    int half = threadIdx.x >> 7;
    int t    = threadIdx.x & 127;
    int b    = blockIdx.x * 2 + half;

    float* h    = hA  + half * 64;
    float* ht   = htA + half * 64;
    float* z    = zA  + half * 128;
    float* ksum = ksA + half * 64;

    uint32_t mb[2];
    mb[0] = (uint32_t)__cvta_generic_to_shared(&mbar_s[half * 2 + 0]);
    mb[1] = (uint32_t)__cvta_generic_to_shared(&mbar_s[half * 2 + 1]);
    uint32_t vs_s[2];
    vs_s[0] = (uint32_t)__cvta_generic_to_shared(VsA + (half * 2 + 0) * VSLC);
    vs_s[1] = (uint32_t)__cvta_generic_to_shared(VsA + (half * 2 + 1) * VSLC);

    if (t == 0) { mbar_init(mb[0], 1); mbar_init(mb[1], 1); }
    hbar(half);

    float w1r[64];
    #pragma unroll
    for (int i = 0; i < 64; ++i) w1r[i] = W1[i * 128 + t];
    float b1t = b1[t];

    if (t < 64) {
        float acc = b_in[t];
        const float* x0 = X + (size_t)b * T_SZ * D_SZ;
        #pragma unroll
        for (int d = 0; d < 64; ++d) acc += x0[d] * W_in[d * 64 + t];
        h[t] = acc; ht[t] = acc; ksum[t] = 0.0f;
    }

    auto prefetch = [&](int n, int buf) {
        if (t == 0) {
            mbar_expect_tx(mb[buf], VBYTES);
            bulk_g2s(vs_s[buf], g_V + (size_t)(b * NI_SZ + n) * NBP, VBYTES, mb[buf]);
        }
    };

    prefetch(0, 0);

    const float wgt[4] = {1.0f, 2.0f, 2.0f, 1.0f};
    const float aco[4] = {0.5f, 0.5f, 1.0f, 0.0f};

    for (int n = 0; n < NI_SZ; ++n) {
        mbar_wait(mb[n & 1], (n >> 1) & 1);
        hbar(half);                       // all half-threads done with interval n-1
        if (n + 1 < NI_SZ) prefetch(n + 1, (n + 1) & 1);
        const float* Vs = VsA + (half * 2 + (n & 1)) * VSLC;

        #pragma unroll
        for (int s = 0; s < 4; ++s) {
            float a0 = b1t, a1 = 0.0f, a2 = 0.0f, a3 = 0.0f;
            #pragma unroll
            for (int i = 0; i < 64; i += 4) {
                a0 += ht[i]     * w1r[i];
                a1 += ht[i + 1] * w1r[i + 1];
                a2 += ht[i + 2] * w1r[i + 2];
                a3 += ht[i + 3] * w1r[i + 3];
            }
            z[t] = tanhf((a0 + a1) + (a2 + a3));
            hbar(half);
            if (t < 64) {
                float k0 = Vs[128 * 64 + t], k1 = 0.0f, k2 = 0.0f, k3 = 0.0f;
                #pragma unroll
                for (int m = 0; m < 128; m += 4) {
                    k0 += z[m]     * Vs[m * 64 + t];
                    k1 += z[m + 1] * Vs[(m + 1) * 64 + t];
                    k2 += z[m + 2] * Vs[(m + 2) * 64 + t];
                    k3 += z[m + 3] * Vs[(m + 3) * 64 + t];
                }
                float ka = (k0 + k1) + (k2 + k3);
                ksum[t] += wgt[s] * ka;
                if (s < 3) ht[t] = h[t] + aco[s] * ka;
            }
            hbar(half);
        }
        if (t < 64) {
            float hn = h[t] + ksum[t] * (1.0f / 6.0f);
            h[t] = hn; ht[t] = hn; ksum[t] = 0.0f;
        }
    }

    if (t < OUT_SZ) {
        float acc = b_out[t];
        #pragma unroll
        for (int d = 0; d < 64; ++d) acc += h[d] * W_out[d * OUT_SZ + t];
        out[b * OUT_SZ + t] = acc;
    }
}

// ---------------------------------------------------------------------------
extern "C" void kernel_launch(void* const* d_in, const int* in_sizes, int n_in,
                              void* d_out, int out_size) {
    const float* X     = (const float*)d_in[0];
    const float* W_in  = (const float*)d_in[1];
    const float* b_in  = (const float*)d_in[2];
    const float* W1    = (const float*)d_in[3];
    const float* b1    = (const float*)d_in[4];
    const float* W2    = (const float*)d_in[5];
    const float* b2    = (const float*)d_in[6];
    const float* W_out = (const float*)d_in[7];
    const float* b_out = (const float*)d_in[8];
    float* out = (float*)d_out;

    (void)in_sizes; (void)n_in; (void)out_size;

    int gemm_smem = 2 * STAGE_B + 1024;                       // 132096
    cudaFuncSetAttribute(gemm_k, cudaFuncAttributeMaxDynamicSharedMemorySize, gemm_smem);
    int scan_smem = (4 * VSLC + 128 + 128 + 256 + 128) * 4;   // 134656
    cudaFuncSetAttribute(scan_k, cudaFuncAttributeMaxDynamicSharedMemorySize, scan_smem);

    prep_B_k<<<NBP, 256>>>(W2, b2);
    logsig_k<<<dim3(NI_SZ, B_SZ), 256>>>(X);
    gemm_k<<<dim3(NBP / BN, BN_TOT / BM), 256, gemm_smem>>>();
    scan_k<<<B_SZ / 2, 256, scan_smem>>>(X, W_in, b_in, W1, b1, W_out, b_out, out);
}